// round 16
// baseline (speedup 1.0000x reference)
#include <cuda_runtime.h>
#include <math.h>

// ---------------- scratch (static device allocations) ----------------
__device__ float g_band[8 * 1024 * 65];   // banded ATA -> L, [b][col][d], fp32
__device__ float g_atb[8 * 1024];         // rhs
__device__ float g_t[2 * 2 * 64 * 1024];  // conv1 outputs [branch][n][c][px]
__device__ float g_att[2 * 24 * 1024];    // sigmoid(conv2 att)
__device__ float g_grad[2 * 24 * 1024];   // conv2 grad
__device__ float g_se[2 * 4];
__device__ float g_sol[8 * 1024];
__device__ float g_ygn[2 * 4 * 1024];

// ---------------- conv1: 64->64 3x3, lrelu, 4 outputs per block ------------
__global__ void __launch_bounds__(256) k_conv1(
    const float* __restrict__ x,
    const float* __restrict__ gw1, const float* __restrict__ gb1,
    const float* __restrict__ aw1, const float* __restrict__ ab1)
{
    int plane  = blockIdx.x;           // 0..63
    int branch = plane >> 5;           // 0=grad, 1=att
    int n      = (plane >> 4) & 1;
    int co0    = (plane & 15) << 2;    // 0,4,..,60
    const float* wbase = (branch ? aw1 : gw1);
    const float* bbase = (branch ? ab1 : gb1);

    __shared__ float xs[34 * 34];
    int row  = threadIdx.x >> 3;        // 0..31
    int col0 = (threadIdx.x & 7) << 2;  // 0..28 step 4

    float acc[4][4];
#pragma unroll
    for (int q = 0; q < 4; q++) {
        float bv = bbase[co0 + q];
#pragma unroll
        for (int p = 0; p < 4; p++) acc[q][p] = bv;
    }
    const float* xbase = x + n * 64 * 1024;

    for (int ci = 0; ci < 64; ci++) {
        __syncthreads();
        const float* xp = xbase + ci * 1024;
        for (int idx = threadIdx.x; idx < 1156; idx += 256) {
            int r = idx / 34, c = idx - r * 34;
            int gr = r - 1, gc = c - 1;
            xs[idx] = ((unsigned)gr < 32u && (unsigned)gc < 32u) ? xp[gr * 32 + gc] : 0.f;
        }
        __syncthreads();
        float w[4][9];
#pragma unroll
        for (int q = 0; q < 4; q++)
#pragma unroll
            for (int k = 0; k < 9; k++)
                w[q][k] = __ldg(wbase + (co0 + q) * 576 + ci * 9 + k);
        float s[3][6];
#pragma unroll
        for (int dy = 0; dy < 3; dy++)
#pragma unroll
            for (int dx = 0; dx < 6; dx++)
                s[dy][dx] = xs[(row + dy) * 34 + col0 + dx];
#pragma unroll
        for (int q = 0; q < 4; q++)
#pragma unroll
            for (int dy = 0; dy < 3; dy++) {
                float w0 = w[q][dy * 3], w1 = w[q][dy * 3 + 1], w2 = w[q][dy * 3 + 2];
                acc[q][0] += w0 * s[dy][0] + w1 * s[dy][1] + w2 * s[dy][2];
                acc[q][1] += w0 * s[dy][1] + w1 * s[dy][2] + w2 * s[dy][3];
                acc[q][2] += w0 * s[dy][2] + w1 * s[dy][3] + w2 * s[dy][4];
                acc[q][3] += w0 * s[dy][3] + w1 * s[dy][4] + w2 * s[dy][5];
            }
    }
#pragma unroll
    for (int q = 0; q < 4; q++) {
        float* out = g_t + (((branch * 2 + n) * 64 + co0 + q) * 1024) + row * 32 + col0;
#pragma unroll
        for (int p = 0; p < 4; p++) {
            float v = acc[q][p];
            out[p] = v > 0.f ? v : 0.01f * v;
        }
    }
}

// ---------------- conv2: 64->24 3x3, 2 outputs per block (+sigmoid att) -----
__global__ void __launch_bounds__(256) k_conv2(
    const float* __restrict__ gw2, const float* __restrict__ gb2,
    const float* __restrict__ aw2, const float* __restrict__ ab2)
{
    int plane  = blockIdx.x;            // 0..47
    int branch = plane / 24;
    int rem    = plane - branch * 24;
    int n      = rem / 12;
    int co0    = (rem - n * 12) * 2;    // 0,2,..,22
    const float* wbase = (branch ? aw2 : gw2);
    const float* wgtA  = wbase + co0 * 576;
    const float* wgtB  = wbase + (co0 + 1) * 576;
    float biasA        = (branch ? ab2 : gb2)[co0];
    float biasB        = (branch ? ab2 : gb2)[co0 + 1];

    __shared__ float xs[34 * 34];
    int row  = threadIdx.x >> 3;
    int col0 = (threadIdx.x & 7) << 2;

    float a0 = biasA, a1 = biasA, a2 = biasA, a3 = biasA;
    float b0 = biasB, b1 = biasB, b2 = biasB, b3 = biasB;
    const float* xbase = g_t + (branch * 2 + n) * 64 * 1024;

    for (int ci = 0; ci < 64; ci++) {
        __syncthreads();
        const float* xp = xbase + ci * 1024;
        for (int idx = threadIdx.x; idx < 1156; idx += 256) {
            int r = idx / 34, c = idx - r * 34;
            int gr = r - 1, gc = c - 1;
            xs[idx] = ((unsigned)gr < 32u && (unsigned)gc < 32u) ? xp[gr * 32 + gc] : 0.f;
        }
        __syncthreads();
        float wA[9], wB[9];
#pragma unroll
        for (int k = 0; k < 9; k++) { wA[k] = __ldg(wgtA + ci * 9 + k);
                                      wB[k] = __ldg(wgtB + ci * 9 + k); }
        float s[3][6];
#pragma unroll
        for (int dy = 0; dy < 3; dy++)
#pragma unroll
            for (int dx = 0; dx < 6; dx++)
                s[dy][dx] = xs[(row + dy) * 34 + col0 + dx];
#pragma unroll
        for (int dy = 0; dy < 3; dy++) {
            float w0 = wA[dy * 3], w1 = wA[dy * 3 + 1], w2 = wA[dy * 3 + 2];
            a0 += w0 * s[dy][0] + w1 * s[dy][1] + w2 * s[dy][2];
            a1 += w0 * s[dy][1] + w1 * s[dy][2] + w2 * s[dy][3];
            a2 += w0 * s[dy][2] + w1 * s[dy][3] + w2 * s[dy][4];
            a3 += w0 * s[dy][3] + w1 * s[dy][4] + w2 * s[dy][5];
            float v0 = wB[dy * 3], v1 = wB[dy * 3 + 1], v2 = wB[dy * 3 + 2];
            b0 += v0 * s[dy][0] + v1 * s[dy][1] + v2 * s[dy][2];
            b1 += v0 * s[dy][1] + v1 * s[dy][2] + v2 * s[dy][3];
            b2 += v0 * s[dy][2] + v1 * s[dy][3] + v2 * s[dy][4];
            b3 += v0 * s[dy][3] + v1 * s[dy][4] + v2 * s[dy][5];
        }
    }
    float* outA = (branch ? g_att : g_grad) + ((n * 24 + co0) * 1024) + row * 32 + col0;
    float* outB = outA + 1024;
    if (branch) {
        outA[0] = 1.f / (1.f + expf(-a0));
        outA[1] = 1.f / (1.f + expf(-a1));
        outA[2] = 1.f / (1.f + expf(-a2));
        outA[3] = 1.f / (1.f + expf(-a3));
        outB[0] = 1.f / (1.f + expf(-b0));
        outB[1] = 1.f / (1.f + expf(-b1));
        outB[2] = 1.f / (1.f + expf(-b2));
        outB[3] = 1.f / (1.f + expf(-b3));
    } else {
        outA[0] = a0; outA[1] = a1; outA[2] = a2; outA[3] = a3;
        outB[0] = b0; outB[1] = b1; outB[2] = b2; outB[3] = b3;
    }
}

// ---------------- SE branch ----------------
__global__ void __launch_bounds__(256) k_se(
    const float* __restrict__ x,
    const float* __restrict__ sw1, const float* __restrict__ sb1,
    const float* __restrict__ sw2, const float* __restrict__ sb2)
{
    int n = blockIdx.x, tid = threadIdx.x;
    __shared__ float red[256];
    __shared__ float pooled[64];
    __shared__ float s1[32];

    int c = tid >> 2, part = tid & 3;
    const float* xp = x + (n * 64 + c) * 1024 + part * 256;
    float s = 0.f;
    for (int i = 0; i < 256; i++) s += xp[i];
    red[tid] = s;
    __syncthreads();
    if (part == 0)
        pooled[c] = (red[tid] + red[tid + 1] + red[tid + 2] + red[tid + 3]) * (1.f / 1024.f);
    __syncthreads();
    if (tid < 32) {
        float a = sb1[tid];
        for (int j = 0; j < 64; j++) a += sw1[tid * 64 + j] * pooled[j];
        s1[tid] = a > 0.f ? a : 0.01f * a;
    }
    __syncthreads();
    if (tid < 4) {
        float a = sb2[tid];
        for (int j = 0; j < 32; j++) a += sw2[tid * 32 + j] * s1[j];
        g_se[n * 4 + tid] = 1.f / (1.f + expf(-a));
    }
}

// ---------------- build banded ATA + ATB: deterministic gather ----------------
__global__ void __launch_bounds__(256) k_build(const float* __restrict__ a)
{
    int t = blockIdx.x * blockDim.x + threadIdx.x;   // 0..8191
    int b = t >> 10;
    int q = t & 1023;
    int n = b >> 2;
    int g = b & 3;
    const int offs[7] = {0, 1, 2, 31, 32, 33, 64};

    float acc[11];
    const int DVALS[11] = {0, 1, 2, 29, 30, 31, 32, 33, 62, 63, 64};
#pragma unroll
    for (int z = 0; z < 11; z++) acc[z] = 0.f;
    acc[0] = 1e-12f;
    float atb = 0.f;

#pragma unroll
    for (int k = 0; k < 6; k++) {
        int ch = g * 6 + k;
        const float* attp  = g_att  + (n * 24 + ch) * 1024;
        const float* gradp = g_grad + (n * 24 + ch) * 1024;
#pragma unroll
        for (int c2 = 0; c2 < 7; c2++) {
            int i = q - offs[c2];
            if (i >= 0) {
                float attv = attp[i];
                float at2  = attv * attv;
                const float* arow = a + (size_t)(i * 6 + k) * 1024;
                float v2 = arow[q];
                if (v2 != 0.f) {
                    atb += v2 * at2 * gradp[i];
                    float w2 = v2 * at2;
#pragma unroll
                    for (int c1 = c2; c1 < 7; c1++) {
                        int col1 = i + offs[c1];
                        if (col1 <= 1023) {
                            float contrib = arow[col1] * w2;
                            int d = offs[c1] - offs[c2];
#pragma unroll
                            for (int z = 0; z < 11; z++)
                                if (DVALS[z] == d) acc[z] += contrib;
                        }
                    }
                }
            }
        }
    }

    float* bc = g_band + ((size_t)b * 1024 + q) * 65;
#pragma unroll
    for (int d = 0; d < 65; d++) {
        float v = 0.f;
#pragma unroll
        for (int z = 0; z < 11; z++)
            if (DVALS[z] == d) v = acc[z];
        bc[d] = v;
    }
    g_atb[b * 1024 + q] = atb;
}

// ---------------- banded Cholesky, fp32, rank-8 PIPELINED --------------------
// Ring W: 80 slots x stride 68 (cols j..j+79). PNL: 2 buffers x 8 ranks x 140
// (zero pad 65..139 makes out-of-band terms exact no-ops). Reads use the
// +139-stride trick: PNL[cb + idx + t*139] = L_t[idx - t].
// Step k (panel j = 8k, PNL(k) precomputed):
//   NEAR: warps 0..15 one chunk each (o=8..15, d0 in {0,32});
//         warp 16 lanes 0..7 fwd-sub r=8..15.            -> barrier
//   CONCURRENT: warp 16 phase A(k+1) on cols j+8..15 (8 serial cols);
//         warps 0..13 far chunks (o=16..71, 8 each = 112);
//         warps 14..15 aux: L writeout (520), commit cols j+72..79,
//         prefetch cols j+80..87, fwd-sub r=16..71.      -> barrier
__global__ void __launch_bounds__(544) k_solve()
{
    const int WS = 68, WTOT = 80 * WS;         // 5440
    int b    = blockIdx.x;
    int tid  = threadIdx.x;
    int wid  = tid >> 5;
    int lane = tid & 31;
    float* band = g_band + (size_t)b * 66560;

    __shared__ float W[5440];
    __shared__ float PNL[2240];        // 2 x 8 x 140
    __shared__ float y_s[1100];
    __shared__ float x_s[1024];

#define CHDO(A, OB, O) { float _w = W[A]; \
        _w -= PNL[cb + (O)]       * PNL[cb + (OB)]; \
        _w -= PNL[cb + (O) + 139] * PNL[cb + (OB) + 139]; \
        _w -= PNL[cb + (O) + 278] * PNL[cb + (OB) + 278]; \
        _w -= PNL[cb + (O) + 417] * PNL[cb + (OB) + 417]; \
        _w -= PNL[cb + (O) + 556] * PNL[cb + (OB) + 556]; \
        _w -= PNL[cb + (O) + 695] * PNL[cb + (OB) + 695]; \
        _w -= PNL[cb + (O) + 834] * PNL[cb + (OB) + 834]; \
        _w -= PNL[cb + (O) + 973] * PNL[cb + (OB) + 973]; \
        W[A] = _w; A += 544; if (A >= WTOT) A -= WTOT; }

    // near chunk (warps 0..15): o = 8..15
    int nA = 0, nOB = 0, nO = 0;
    if (wid < 16) {
        int o = 8 + (wid >> 1), d0 = (wid & 1) << 5;
        nA = o * WS + d0 + lane; nOB = o + d0 + lane; nO = o;
    }
    // far chunks (warps 0..13): o = 16..71, exactly 112 chunks
    int fA[8], fOB[8], fO[8];
    if (wid < 14) {
#pragma unroll
        for (int i = 0; i < 8; i++) {
            int idx = wid * 8 + i;
            int o = 16 + (idx >> 1), d0 = (idx & 1) << 5;
            fA[i] = o * WS + d0 + lane; fOB[i] = o + d0 + lane; fO[i] = o;
        }
    }
    // aux (warps 14,15): lane2 = 0..63, 9 sub-iters cover 520 entries
    int lane2 = (wid - 14) * 32 + lane;
    int aS[9], aA[9], aP[9]; float aV[9];
    if (wid >= 14 && wid < 16) {
#pragma unroll
        for (int i = 0; i < 9; i++) {
            int idx = lane2 + 64 * i;
            int u = idx / 65, dc = idx - u * 65;
            aS[i] = u * 140 + dc;
            aA[i] = (72 + u) * WS + dc;
            aP[i] = 5200 + idx;                // cols 80.. prefetch
            aV[i] = 0.f;
        }
    }
    int jw = 0;

    // ---- init ----
    for (int i = tid; i < 1024; i += 544) y_s[i] = g_atb[b * 1024 + i];
    for (int i = 1024 + tid; i < 1100; i += 544) y_s[i] = 0.f;
    for (int i = tid; i < 5440; i += 544) W[i] = 0.f;
    __syncthreads();
    for (int i = tid; i < 4680; i += 544) {    // cols 0..71
        int c = i / 65, d = i - c * 65;
        W[c * WS + d] = band[i];
    }
    for (int i = tid; i < 2240; i += 544) PNL[i] = 0.f;
    if (wid >= 14 && wid < 16) {
#pragma unroll
        for (int i = 0; i < 9; i++) {
            int idx = lane2 + 64 * i;
            if (idx < 520) aV[i] = band[4680 + idx];   // cols 72..79
        }
    }
    __syncthreads();

    int pa = 0;
    auto phaseA = [&](int j4, int nb) {
        float wa[8], wb[8], w64[8];
#pragma unroll
        for (int t = 0; t < 8; t++) {
            wa[t]  = W[pa + t * WS + lane];
            wb[t]  = W[pa + t * WS + 32 + lane];
            w64[t] = W[pa + t * WS + 64];
        }
        float xv[8];
#pragma unroll
        for (int t = 0; t < 8; t++) {
#pragma unroll
            for (int tp = 0; tp < 8; tp++) {
                if (tp < t) {
                    int bidx = nb + tp * 140 + (t - tp);
                    float lp = PNL[bidx];
                    wa[t] -= lp * PNL[bidx + lane];
                    wb[t] -= lp * PNL[bidx + 32 + lane];
                }
            }
            float piv = __shfl_sync(0xffffffffu, wa[t], 0);
            float rr  = rsqrtf(piv);
            float inv = rr * (1.5f - 0.5f * piv * rr * rr);
            PNL[nb + t * 140 + lane]      = (lane == 0) ? inv : wa[t] * inv;
            PNL[nb + t * 140 + 32 + lane] = wb[t] * inv;
            if (lane == 0) {
                PNL[nb + t * 140 + 64] = w64[t] * inv;
                float acc = y_s[j4 + t];
#pragma unroll
                for (int tp = 0; tp < 8; tp++)
                    if (tp < t) acc -= PNL[nb + tp * 140 + (t - tp)] * xv[tp];
                xv[t] = acc * inv;
                x_s[j4 + t] = xv[t];
            }
            __syncwarp();
        }
        pa += 544; if (pa >= WTOT) pa -= WTOT;
    };

    // ---- prologue: Phase A(0) on cols 0..7 (buffer 0) ----
    if (wid == 16) phaseA(0, 0);
    __syncthreads();

    // ---- main loop: one pipelined step per rank-8 panel ----
    for (int k = 0; k < 128; k++) {
        int j  = k << 3;
        int cb = (k & 1) * 1120;

        // ===== NEAR =====
        if (wid < 16) {
            CHDO(nA, nOB, nO)
        } else if (wid == 16 && lane < 8) {
            int r = 8 + lane;
            float yv = y_s[j + r];
#pragma unroll
            for (int t = 0; t < 8; t++)
                yv -= PNL[cb + r + t * 139] * x_s[j + t];
            y_s[j + r] = yv;
        }
        __syncthreads();

        // ===== CONCURRENT =====
        if (wid == 16) {
            if (k < 127) phaseA(j + 8, 1120 - cb);
        } else if (wid < 14) {
            CHDO(fA[0], fOB[0], fO[0])
            CHDO(fA[1], fOB[1], fO[1])
            CHDO(fA[2], fOB[2], fO[2])
            CHDO(fA[3], fOB[3], fO[3])
            CHDO(fA[4], fOB[4], fO[4])
            CHDO(fA[5], fOB[5], fO[5])
            CHDO(fA[6], fOB[6], fO[6])
            CHDO(fA[7], fOB[7], fO[7])
        } else {
#pragma unroll
            for (int i = 0; i < 9; i++) {
                if (i < 8 || lane2 < 8) {
                    band[jw + lane2 + 64 * i] = PNL[cb + aS[i]];   // L writeout
                    W[aA[i]] = aV[i];                              // commit
                    aA[i] += 544; if (aA[i] >= WTOT) aA[i] -= WTOT;
                    aV[i] = (aP[i] < 66560) ? band[aP[i]] : 0.f;   // prefetch
                    aP[i] += 520;
                }
            }
            jw += 520;
            if (lane2 < 56) {
                int r = 16 + lane2;
                float yv = y_s[j + r];
                float x0 = x_s[j],     x1 = x_s[j + 1], x2 = x_s[j + 2], x3 = x_s[j + 3];
                float x4 = x_s[j + 4], x5 = x_s[j + 5], x6 = x_s[j + 6], x7 = x_s[j + 7];
                yv -= PNL[cb + r]       * x0;
                yv -= PNL[cb + r + 139] * x1;
                yv -= PNL[cb + r + 278] * x2;
                yv -= PNL[cb + r + 417] * x3;
                yv -= PNL[cb + r + 556] * x4;
                yv -= PNL[cb + r + 695] * x5;
                yv -= PNL[cb + r + 834] * x6;
                yv -= PNL[cb + r + 973] * x7;
                y_s[j + r] = yv;
            }
        }
        __syncthreads();
    }
#undef CHDO

    // ---- back substitution: L^T x = y', blocked by 64 rows (reuse W) ----
    float* LB = W;   // stride-65 layout
    for (int blk = 15; blk >= 0; blk--) {
        int j0 = blk * 64;
        for (int idx = tid; idx < 64 * 65; idx += 544)
            LB[idx] = band[j0 * 65 + idx];
        __syncthreads();
        if (tid < 64) {
            int t = tid, jj = j0 + t;
            float s = 0.f;
            for (int r = 64 - t; r <= 64; r++) {
                int jr = jj + r;
                if (jr < 1024) s += LB[t * 65 + r] * x_s[jr];
            }
            x_s[jj] -= s;
        }
        __syncthreads();
        for (int t = 63; t >= 1; t--) {
            float xval = x_s[j0 + t] * LB[t * 65];
            if (tid < t) x_s[j0 + tid] -= LB[tid * 65 + (t - tid)] * xval;
            __syncthreads();
        }
        if (tid < 64) x_s[j0 + tid] *= LB[tid * 65];
        __syncthreads();
    }

    for (int i = tid; i < 1024; i += 544) g_sol[b * 1024 + i] = x_s[i];
}

// ---------------- GroupNorm(1, GR) + affine + SE scale ----------------
__global__ void __launch_bounds__(256) k_gn(const float* __restrict__ gn_g,
                                            const float* __restrict__ gn_b)
{
    int n = blockIdx.x, tid = threadIdx.x;
    __shared__ double s1[256], s2[256];
    double a = 0.0, c = 0.0;
    for (int idx = tid; idx < 4096; idx += 256) {
        double v = g_sol[n * 4096 + idx];
        a += v; c += v * v;
    }
    s1[tid] = a; s2[tid] = c;
    __syncthreads();
    for (int off = 128; off > 0; off >>= 1) {
        if (tid < off) { s1[tid] += s1[tid + off]; s2[tid] += s2[tid + off]; }
        __syncthreads();
    }
    double mu  = s1[0] * (1.0 / 4096.0);
    double var = s2[0] * (1.0 / 4096.0) - mu * mu;
    double invstd = rsqrt(var + 1e-5);
    for (int idx = tid; idx < 4096; idx += 256) {
        int g = idx >> 10;
        float v = (float)((g_sol[n * 4096 + idx] - mu) * invstd);
        v = v * gn_g[g] + gn_b[g];
        v *= g_se[n * 4 + g];
        g_ygn[n * 4096 + idx] = v;
    }
}

// ---------------- final conv: 4->128 3x3 ----------------
__global__ void __launch_bounds__(256) k_convf(
    const float* __restrict__ pw, const float* __restrict__ pb,
    float* __restrict__ out)
{
    int plane = blockIdx.x;          // 0..255
    int n  = plane >> 7;
    int co = plane & 127;
    __shared__ float ys[4 * 1156];
    for (int idx = threadIdx.x; idx < 4 * 1156; idx += 256) {
        int ci = idx / 1156, rr = idx - ci * 1156;
        int r = rr / 34, c = rr - r * 34;
        int gr = r - 1, gc = c - 1;
        ys[idx] = ((unsigned)gr < 32u && (unsigned)gc < 32u)
                  ? g_ygn[(n * 4 + ci) * 1024 + gr * 32 + gc] : 0.f;
    }
    __syncthreads();

    const float* wgt = pw + co * 36;
    float bias = pb[co];
    int row  = threadIdx.x >> 3;
    int col0 = (threadIdx.x & 7) << 2;
    float a0 = bias, a1 = bias, a2 = bias, a3 = bias;
#pragma unroll
    for (int ci = 0; ci < 4; ci++) {
        float w[9];
#pragma unroll
        for (int k = 0; k < 9; k++) w[k] = __ldg(wgt + ci * 9 + k);
        float s[3][6];
#pragma unroll
        for (int dy = 0; dy < 3; dy++)
#pragma unroll
            for (int dx = 0; dx < 6; dx++)
                s[dy][dx] = ys[ci * 1156 + (row + dy) * 34 + col0 + dx];
#pragma unroll
        for (int dy = 0; dy < 3; dy++) {
            float w0 = w[dy * 3], w1 = w[dy * 3 + 1], w2 = w[dy * 3 + 2];
            a0 += w0 * s[dy][0] + w1 * s[dy][1] + w2 * s[dy][2];
            a1 += w0 * s[dy][1] + w1 * s[dy][2] + w2 * s[dy][3];
            a2 += w0 * s[dy][2] + w1 * s[dy][3] + w2 * s[dy][4];
            a3 += w0 * s[dy][3] + w1 * s[dy][4] + w2 * s[dy][5];
        }
    }
    float* o = out + ((n * 128 + co) * 1024) + row * 32 + col0;
    o[0] = a0; o[1] = a1; o[2] = a2; o[3] = a3;
}

// ---------------- launcher (k_solve stays the 4th launch) -------------------
extern "C" void kernel_launch(void* const* d_in, const int* in_sizes, int n_in,
                              void* d_out, int out_size)
{
    const float* x    = (const float*)d_in[0];
    const float* a    = (const float*)d_in[1];
    const float* gw1  = (const float*)d_in[2];
    const float* gb1  = (const float*)d_in[3];
    const float* gw2  = (const float*)d_in[4];
    const float* gb2  = (const float*)d_in[5];
    const float* aw1  = (const float*)d_in[6];
    const float* ab1  = (const float*)d_in[7];
    const float* aw2  = (const float*)d_in[8];
    const float* ab2  = (const float*)d_in[9];
    const float* sw1  = (const float*)d_in[10];
    const float* sb1  = (const float*)d_in[11];
    const float* sw2  = (const float*)d_in[12];
    const float* sb2  = (const float*)d_in[13];
    const float* gn_g = (const float*)d_in[14];
    const float* gn_b = (const float*)d_in[15];
    const float* pw   = (const float*)d_in[16];
    const float* pb   = (const float*)d_in[17];
    float* out = (float*)d_out;

    k_conv1<<<64, 256>>>(x, gw1, gb1, aw1, ab1);
    k_conv2<<<48, 256>>>(gw2, gb2, aw2, ab2);
    k_build<<<32, 256>>>(a);
    k_solve<<<8, 544>>>();
    k_se<<<2, 256>>>(x, sw1, sb1, sw2, sb2);
    k_gn<<<2, 256>>>(gn_g, gn_b);
    k_convf<<<256, 256>>>(pw, pb, out);
}

// round 17
// speedup vs baseline: 1.0896x; 1.0896x over previous
#include <cuda_runtime.h>
#include <math.h>

// ---------------- scratch (static device allocations) ----------------
__device__ float g_band[8 * 1024 * 65];   // banded ATA -> L, [b][col][d], fp32
__device__ float g_atb[8 * 1024];         // rhs
__device__ float g_t[2 * 2 * 64 * 1024];  // conv1 outputs [branch][n][c][px]
__device__ float g_att[2 * 24 * 1024];    // sigmoid(conv2 att)
__device__ float g_grad[2 * 24 * 1024];   // conv2 grad
__device__ float g_se[2 * 4];
__device__ float g_sol[8 * 1024];
__device__ float g_ygn[2 * 4 * 1024];

// ---------------- conv1: 64->64 3x3, lrelu, 2 outputs per block ------------
__global__ void __launch_bounds__(256) k_conv1(
    const float* __restrict__ x,
    const float* __restrict__ gw1, const float* __restrict__ gb1,
    const float* __restrict__ aw1, const float* __restrict__ ab1)
{
    int plane  = blockIdx.x;           // 0..127
    int branch = plane >> 6;           // 0=grad, 1=att
    int n      = (plane >> 5) & 1;
    int co0    = (plane & 31) << 1;    // 0,2,..,62
    const float* wbase = (branch ? aw1 : gw1);
    const float* wgtA  = wbase + co0 * 576;
    const float* wgtB  = wbase + (co0 + 1) * 576;
    float biasA        = (branch ? ab1 : gb1)[co0];
    float biasB        = (branch ? ab1 : gb1)[co0 + 1];

    __shared__ float xs[34 * 34];
    int row  = threadIdx.x >> 3;        // 0..31
    int col0 = (threadIdx.x & 7) << 2;  // 0..28 step 4

    float a0 = biasA, a1 = biasA, a2 = biasA, a3 = biasA;
    float b0 = biasB, b1 = biasB, b2 = biasB, b3 = biasB;
    const float* xbase = x + n * 64 * 1024;

    for (int ci = 0; ci < 64; ci++) {
        __syncthreads();
        const float* xp = xbase + ci * 1024;
        for (int idx = threadIdx.x; idx < 1156; idx += 256) {
            int r = idx / 34, c = idx - r * 34;
            int gr = r - 1, gc = c - 1;
            xs[idx] = ((unsigned)gr < 32u && (unsigned)gc < 32u) ? xp[gr * 32 + gc] : 0.f;
        }
        __syncthreads();
        float wA[9], wB[9];
#pragma unroll
        for (int k = 0; k < 9; k++) { wA[k] = __ldg(wgtA + ci * 9 + k);
                                      wB[k] = __ldg(wgtB + ci * 9 + k); }
        float s[3][6];
#pragma unroll
        for (int dy = 0; dy < 3; dy++)
#pragma unroll
            for (int dx = 0; dx < 6; dx++)
                s[dy][dx] = xs[(row + dy) * 34 + col0 + dx];
#pragma unroll
        for (int dy = 0; dy < 3; dy++) {
            float w0 = wA[dy * 3], w1 = wA[dy * 3 + 1], w2 = wA[dy * 3 + 2];
            a0 += w0 * s[dy][0] + w1 * s[dy][1] + w2 * s[dy][2];
            a1 += w0 * s[dy][1] + w1 * s[dy][2] + w2 * s[dy][3];
            a2 += w0 * s[dy][2] + w1 * s[dy][3] + w2 * s[dy][4];
            a3 += w0 * s[dy][3] + w1 * s[dy][4] + w2 * s[dy][5];
            float v0 = wB[dy * 3], v1 = wB[dy * 3 + 1], v2 = wB[dy * 3 + 2];
            b0 += v0 * s[dy][0] + v1 * s[dy][1] + v2 * s[dy][2];
            b1 += v0 * s[dy][1] + v1 * s[dy][2] + v2 * s[dy][3];
            b2 += v0 * s[dy][2] + v1 * s[dy][3] + v2 * s[dy][4];
            b3 += v0 * s[dy][3] + v1 * s[dy][4] + v2 * s[dy][5];
        }
    }
    float* outA = g_t + (((branch * 2 + n) * 64 + co0) * 1024) + row * 32 + col0;
    float* outB = outA + 1024;
    outA[0] = a0 > 0.f ? a0 : 0.01f * a0;
    outA[1] = a1 > 0.f ? a1 : 0.01f * a1;
    outA[2] = a2 > 0.f ? a2 : 0.01f * a2;
    outA[3] = a3 > 0.f ? a3 : 0.01f * a3;
    outB[0] = b0 > 0.f ? b0 : 0.01f * b0;
    outB[1] = b1 > 0.f ? b1 : 0.01f * b1;
    outB[2] = b2 > 0.f ? b2 : 0.01f * b2;
    outB[3] = b3 > 0.f ? b3 : 0.01f * b3;
}

// ---------------- conv2: 64->24 3x3 (+sigmoid on att branch) ----------------
__global__ void __launch_bounds__(256) k_conv2(
    const float* __restrict__ gw2, const float* __restrict__ gb2,
    const float* __restrict__ aw2, const float* __restrict__ ab2)
{
    int plane  = blockIdx.x;            // 0..95
    int branch = plane / 48;
    int rem    = plane - branch * 48;
    int n      = rem / 24;
    int co     = rem - n * 24;
    const float* wgt = (branch ? aw2 : gw2) + co * 576;
    float bias       = (branch ? ab2 : gb2)[co];

    __shared__ float xs[34 * 34];
    int row  = threadIdx.x >> 3;
    int col0 = (threadIdx.x & 7) << 2;

    float a0 = bias, a1 = bias, a2 = bias, a3 = bias;
    const float* xbase = g_t + (branch * 2 + n) * 64 * 1024;

    for (int ci = 0; ci < 64; ci++) {
        __syncthreads();
        const float* xp = xbase + ci * 1024;
        for (int idx = threadIdx.x; idx < 1156; idx += 256) {
            int r = idx / 34, c = idx - r * 34;
            int gr = r - 1, gc = c - 1;
            xs[idx] = ((unsigned)gr < 32u && (unsigned)gc < 32u) ? xp[gr * 32 + gc] : 0.f;
        }
        __syncthreads();
        float w[9];
#pragma unroll
        for (int k = 0; k < 9; k++) w[k] = __ldg(wgt + ci * 9 + k);
        float s[3][6];
#pragma unroll
        for (int dy = 0; dy < 3; dy++)
#pragma unroll
            for (int dx = 0; dx < 6; dx++)
                s[dy][dx] = xs[(row + dy) * 34 + col0 + dx];
#pragma unroll
        for (int dy = 0; dy < 3; dy++) {
            float w0 = w[dy * 3], w1 = w[dy * 3 + 1], w2 = w[dy * 3 + 2];
            a0 += w0 * s[dy][0] + w1 * s[dy][1] + w2 * s[dy][2];
            a1 += w0 * s[dy][1] + w1 * s[dy][2] + w2 * s[dy][3];
            a2 += w0 * s[dy][2] + w1 * s[dy][3] + w2 * s[dy][4];
            a3 += w0 * s[dy][3] + w1 * s[dy][4] + w2 * s[dy][5];
        }
    }
    float* out = (branch ? g_att : g_grad) + ((n * 24 + co) * 1024) + row * 32 + col0;
    if (branch) {
        out[0] = 1.f / (1.f + expf(-a0));
        out[1] = 1.f / (1.f + expf(-a1));
        out[2] = 1.f / (1.f + expf(-a2));
        out[3] = 1.f / (1.f + expf(-a3));
    } else {
        out[0] = a0; out[1] = a1; out[2] = a2; out[3] = a3;
    }
}

// ---------------- SE branch ----------------
__global__ void __launch_bounds__(256) k_se(
    const float* __restrict__ x,
    const float* __restrict__ sw1, const float* __restrict__ sb1,
    const float* __restrict__ sw2, const float* __restrict__ sb2)
{
    int n = blockIdx.x, tid = threadIdx.x;
    __shared__ float red[256];
    __shared__ float pooled[64];
    __shared__ float s1[32];

    int c = tid >> 2, part = tid & 3;
    const float* xp = x + (n * 64 + c) * 1024 + part * 256;
    float s = 0.f;
    for (int i = 0; i < 256; i++) s += xp[i];
    red[tid] = s;
    __syncthreads();
    if (part == 0)
        pooled[c] = (red[tid] + red[tid + 1] + red[tid + 2] + red[tid + 3]) * (1.f / 1024.f);
    __syncthreads();
    if (tid < 32) {
        float a = sb1[tid];
        for (int j = 0; j < 64; j++) a += sw1[tid * 64 + j] * pooled[j];
        s1[tid] = a > 0.f ? a : 0.01f * a;
    }
    __syncthreads();
    if (tid < 4) {
        float a = sb2[tid];
        for (int j = 0; j < 32; j++) a += sw2[tid * 32 + j] * s1[j];
        g_se[n * 4 + tid] = 1.f / (1.f + expf(-a));
    }
}

// ---------------- build banded ATA + ATB: deterministic gather ----------------
__global__ void __launch_bounds__(256) k_build(const float* __restrict__ a)
{
    int t = blockIdx.x * blockDim.x + threadIdx.x;   // 0..8191
    int b = t >> 10;
    int q = t & 1023;
    int n = b >> 2;
    int g = b & 3;
    const int offs[7] = {0, 1, 2, 31, 32, 33, 64};

    float acc[11];
    const int DVALS[11] = {0, 1, 2, 29, 30, 31, 32, 33, 62, 63, 64};
#pragma unroll
    for (int z = 0; z < 11; z++) acc[z] = 0.f;
    acc[0] = 1e-12f;
    float atb = 0.f;

#pragma unroll
    for (int k = 0; k < 6; k++) {
        int ch = g * 6 + k;
        const float* attp  = g_att  + (n * 24 + ch) * 1024;
        const float* gradp = g_grad + (n * 24 + ch) * 1024;
#pragma unroll
        for (int c2 = 0; c2 < 7; c2++) {
            int i = q - offs[c2];
            if (i >= 0) {
                float attv = attp[i];
                float at2  = attv * attv;
                const float* arow = a + (size_t)(i * 6 + k) * 1024;
                float v2 = arow[q];
                if (v2 != 0.f) {
                    atb += v2 * at2 * gradp[i];
                    float w2 = v2 * at2;
#pragma unroll
                    for (int c1 = c2; c1 < 7; c1++) {
                        int col1 = i + offs[c1];
                        if (col1 <= 1023) {
                            float contrib = arow[col1] * w2;
                            int d = offs[c1] - offs[c2];
#pragma unroll
                            for (int z = 0; z < 11; z++)
                                if (DVALS[z] == d) acc[z] += contrib;
                        }
                    }
                }
            }
        }
    }

    float* bc = g_band + ((size_t)b * 1024 + q) * 65;
#pragma unroll
    for (int d = 0; d < 65; d++) {
        float v = 0.f;
#pragma unroll
        for (int z = 0; z < 11; z++)
            if (DVALS[z] == d) v = acc[z];
        bc[d] = v;
    }
    g_atb[b * 1024 + q] = atb;
}

// ---------------- banded Cholesky, fp32, rank-8 PIPELINED, shuffle Phase A ---
// Ring W: 80 slots x stride 68 (cols j..j+79). PNL: 2 buffers x 8 ranks x 140
// (zero pad 65..139 makes out-of-band terms exact no-ops). Worker reads use the
// +139-stride trick: PNL[cb + idx + t*139] = L_t[idx - t].
// Phase A is register-resident: intra-panel corrections are RIGHT-looking via
// warp shuffles of the just-scaled column (no smem round-trip on the critical
// chain). Identical arithmetic order per cell as the left-looking version.
__global__ void __launch_bounds__(544) k_solve()
{
    const int WS = 68, WTOT = 80 * WS;         // 5440
    int b    = blockIdx.x;
    int tid  = threadIdx.x;
    int wid  = tid >> 5;
    int lane = tid & 31;
    float* band = g_band + (size_t)b * 66560;

    __shared__ float W[5440];
    __shared__ float PNL[2240];        // 2 x 8 x 140
    __shared__ float y_s[1100];
    __shared__ float x_s[1024];

#define CHDO(A, OB, O) { float _w = W[A]; \
        _w -= PNL[cb + (O)]       * PNL[cb + (OB)]; \
        _w -= PNL[cb + (O) + 139] * PNL[cb + (OB) + 139]; \
        _w -= PNL[cb + (O) + 278] * PNL[cb + (OB) + 278]; \
        _w -= PNL[cb + (O) + 417] * PNL[cb + (OB) + 417]; \
        _w -= PNL[cb + (O) + 556] * PNL[cb + (OB) + 556]; \
        _w -= PNL[cb + (O) + 695] * PNL[cb + (OB) + 695]; \
        _w -= PNL[cb + (O) + 834] * PNL[cb + (OB) + 834]; \
        _w -= PNL[cb + (O) + 973] * PNL[cb + (OB) + 973]; \
        W[A] = _w; A += 544; if (A >= WTOT) A -= WTOT; }

    // near chunk (warps 0..15): o = 8..15
    int nA = 0, nOB = 0, nO = 0;
    if (wid < 16) {
        int o = 8 + (wid >> 1), d0 = (wid & 1) << 5;
        nA = o * WS + d0 + lane; nOB = o + d0 + lane; nO = o;
    }
    // far chunks (warps 0..13): o = 16..71, exactly 112 chunks
    int fA[8], fOB[8], fO[8];
    if (wid < 14) {
#pragma unroll
        for (int i = 0; i < 8; i++) {
            int idx = wid * 8 + i;
            int o = 16 + (idx >> 1), d0 = (idx & 1) << 5;
            fA[i] = o * WS + d0 + lane; fOB[i] = o + d0 + lane; fO[i] = o;
        }
    }
    // aux (warps 14,15): lane2 = 0..63, 9 sub-iters cover 520 entries
    int lane2 = (wid - 14) * 32 + lane;
    int aS[9], aA[9], aP[9]; float aV[9];
    if (wid >= 14 && wid < 16) {
#pragma unroll
        for (int i = 0; i < 9; i++) {
            int idx = lane2 + 64 * i;
            int u = idx / 65, dc = idx - u * 65;
            aS[i] = u * 140 + dc;
            aA[i] = (72 + u) * WS + dc;
            aP[i] = 5200 + idx;                // cols 80.. prefetch
            aV[i] = 0.f;
        }
    }
    int jw = 0;

    // ---- init ----
    for (int i = tid; i < 1024; i += 544) y_s[i] = g_atb[b * 1024 + i];
    for (int i = 1024 + tid; i < 1100; i += 544) y_s[i] = 0.f;
    for (int i = tid; i < 5440; i += 544) W[i] = 0.f;
    __syncthreads();
    for (int i = tid; i < 4680; i += 544) {    // cols 0..71
        int c = i / 65, d = i - c * 65;
        W[c * WS + d] = band[i];
    }
    for (int i = tid; i < 2240; i += 544) PNL[i] = 0.f;
    if (wid >= 14 && wid < 16) {
#pragma unroll
        for (int i = 0; i < 9; i++) {
            int idx = lane2 + 64 * i;
            if (idx < 520) aV[i] = band[4680 + idx];   // cols 72..79
        }
    }
    __syncthreads();

    int pa = 0;
    auto phaseA = [&](int j4, int nb) {
        float wa[8], wb[8], w64v[8], yreg[8];
#pragma unroll
        for (int t = 0; t < 8; t++) {
            wa[t]   = W[pa + t * WS + lane];
            wb[t]   = W[pa + t * WS + 32 + lane];
            w64v[t] = W[pa + t * WS + 64];
            yreg[t] = y_s[j4 + t];
        }
#pragma unroll
        for (int t = 0; t < 8; t++) {
            float piv = __shfl_sync(0xffffffffu, wa[t], 0);
            float rr  = rsqrtf(piv);
            float inv = rr * (1.5f - 0.5f * piv * rr * rr);
            float sa  = wa[t] * inv;       // lane i = L_t[i]
            float sb  = wb[t] * inv;       // lane i = L_t[32+i]
            float s64 = w64v[t] * inv;     // L_t[64]
            // publish (lane0 stores INVERSE diag per convention)
            PNL[nb + t * 140 + lane]      = (lane == 0) ? inv : sa;
            PNL[nb + t * 140 + 32 + lane] = sb;
            if (lane == 0) PNL[nb + t * 140 + 64] = s64;
            float xvt = yreg[t] * inv;     // broadcast-consistent on all lanes
            if (lane == 0) x_s[j4 + t] = xvt;
            // right-looking intra-panel updates via shuffles
#pragma unroll
            for (int tq = t + 1; tq < 8; tq++) {
                const int delta = tq - t;                    // 1..7 (compile-time)
                float lp    = __shfl_sync(0xffffffffu, sa, delta);
                float va_lo = __shfl_down_sync(0xffffffffu, sa, delta);
                float va_hi = __shfl_sync(0xffffffffu, sb, lane + delta - 32);
                float va    = (lane + delta < 32) ? va_lo : va_hi;
                float vb_lo = __shfl_down_sync(0xffffffffu, sb, delta);
                float vb    = (lane + delta < 32) ? vb_lo
                              : ((lane + delta == 32) ? s64 : 0.f);
                wa[tq] -= lp * va;
                wb[tq] -= lp * vb;
                yreg[tq] -= lp * xvt;
            }
        }
        pa += 544; if (pa >= WTOT) pa -= WTOT;
    };

    // ---- prologue: Phase A(0) on cols 0..7 (buffer 0) ----
    if (wid == 16) phaseA(0, 0);
    __syncthreads();

    // ---- main loop: one pipelined step per rank-8 panel ----
    for (int k = 0; k < 128; k++) {
        int j  = k << 3;
        int cb = (k & 1) * 1120;

        // ===== NEAR =====
        if (wid < 16) {
            CHDO(nA, nOB, nO)
        } else if (wid == 16 && lane < 8) {
            int r = 8 + lane;
            float yv = y_s[j + r];
#pragma unroll
            for (int t = 0; t < 8; t++)
                yv -= PNL[cb + r + t * 139] * x_s[j + t];
            y_s[j + r] = yv;
        }
        __syncthreads();

        // ===== CONCURRENT =====
        if (wid == 16) {
            if (k < 127) phaseA(j + 8, 1120 - cb);
        } else if (wid < 14) {
            CHDO(fA[0], fOB[0], fO[0])
            CHDO(fA[1], fOB[1], fO[1])
            CHDO(fA[2], fOB[2], fO[2])
            CHDO(fA[3], fOB[3], fO[3])
            CHDO(fA[4], fOB[4], fO[4])
            CHDO(fA[5], fOB[5], fO[5])
            CHDO(fA[6], fOB[6], fO[6])
            CHDO(fA[7], fOB[7], fO[7])
        } else {
#pragma unroll
            for (int i = 0; i < 9; i++) {
                if (i < 8 || lane2 < 8) {
                    band[jw + lane2 + 64 * i] = PNL[cb + aS[i]];   // L writeout
                    W[aA[i]] = aV[i];                              // commit
                    aA[i] += 544; if (aA[i] >= WTOT) aA[i] -= WTOT;
                    aV[i] = (aP[i] < 66560) ? band[aP[i]] : 0.f;   // prefetch
                    aP[i] += 520;
                }
            }
            jw += 520;
            if (lane2 < 56) {
                int r = 16 + lane2;
                float yv = y_s[j + r];
                float x0 = x_s[j],     x1 = x_s[j + 1], x2 = x_s[j + 2], x3 = x_s[j + 3];
                float x4 = x_s[j + 4], x5 = x_s[j + 5], x6 = x_s[j + 6], x7 = x_s[j + 7];
                yv -= PNL[cb + r]       * x0;
                yv -= PNL[cb + r + 139] * x1;
                yv -= PNL[cb + r + 278] * x2;
                yv -= PNL[cb + r + 417] * x3;
                yv -= PNL[cb + r + 556] * x4;
                yv -= PNL[cb + r + 695] * x5;
                yv -= PNL[cb + r + 834] * x6;
                yv -= PNL[cb + r + 973] * x7;
                y_s[j + r] = yv;
            }
        }
        __syncthreads();
    }
#undef CHDO

    // ---- back substitution: L^T x = y', blocked by 64 rows (reuse W) ----
    float* LB = W;   // stride-65 layout
    for (int blk = 15; blk >= 0; blk--) {
        int j0 = blk * 64;
        for (int idx = tid; idx < 64 * 65; idx += 544)
            LB[idx] = band[j0 * 65 + idx];
        __syncthreads();
        if (tid < 64) {
            int t = tid, jj = j0 + t;
            float s = 0.f;
            for (int r = 64 - t; r <= 64; r++) {
                int jr = jj + r;
                if (jr < 1024) s += LB[t * 65 + r] * x_s[jr];
            }
            x_s[jj] -= s;
        }
        __syncthreads();
        for (int t = 63; t >= 1; t--) {
            float xval = x_s[j0 + t] * LB[t * 65];
            if (tid < t) x_s[j0 + tid] -= LB[tid * 65 + (t - tid)] * xval;
            __syncthreads();
        }
        if (tid < 64) x_s[j0 + tid] *= LB[tid * 65];
        __syncthreads();
    }

    for (int i = tid; i < 1024; i += 544) g_sol[b * 1024 + i] = x_s[i];
}

// ---------------- GroupNorm(1, GR) + affine + SE scale ----------------
__global__ void __launch_bounds__(256) k_gn(const float* __restrict__ gn_g,
                                            const float* __restrict__ gn_b)
{
    int n = blockIdx.x, tid = threadIdx.x;
    __shared__ double s1[256], s2[256];
    double a = 0.0, c = 0.0;
    for (int idx = tid; idx < 4096; idx += 256) {
        double v = g_sol[n * 4096 + idx];
        a += v; c += v * v;
    }
    s1[tid] = a; s2[tid] = c;
    __syncthreads();
    for (int off = 128; off > 0; off >>= 1) {
        if (tid < off) { s1[tid] += s1[tid + off]; s2[tid] += s2[tid + off]; }
        __syncthreads();
    }
    double mu  = s1[0] * (1.0 / 4096.0);
    double var = s2[0] * (1.0 / 4096.0) - mu * mu;
    double invstd = rsqrt(var + 1e-5);
    for (int idx = tid; idx < 4096; idx += 256) {
        int g = idx >> 10;
        float v = (float)((g_sol[n * 4096 + idx] - mu) * invstd);
        v = v * gn_g[g] + gn_b[g];
        v *= g_se[n * 4 + g];
        g_ygn[n * 4096 + idx] = v;
    }
}

// ---------------- final conv: 4->128 3x3 ----------------
__global__ void __launch_bounds__(256) k_convf(
    const float* __restrict__ pw, const float* __restrict__ pb,
    float* __restrict__ out)
{
    int plane = blockIdx.x;          // 0..255
    int n  = plane >> 7;
    int co = plane & 127;
    __shared__ float ys[4 * 1156];
    for (int idx = threadIdx.x; idx < 4 * 1156; idx += 256) {
        int ci = idx / 1156, rr = idx - ci * 1156;
        int r = rr / 34, c = rr - r * 34;
        int gr = r - 1, gc = c - 1;
        ys[idx] = ((unsigned)gr < 32u && (unsigned)gc < 32u)
                  ? g_ygn[(n * 4 + ci) * 1024 + gr * 32 + gc] : 0.f;
    }
    __syncthreads();

    const float* wgt = pw + co * 36;
    float bias = pb[co];
    int row  = threadIdx.x >> 3;
    int col0 = (threadIdx.x & 7) << 2;
    float a0 = bias, a1 = bias, a2 = bias, a3 = bias;
#pragma unroll
    for (int ci = 0; ci < 4; ci++) {
        float w[9];
#pragma unroll
        for (int k = 0; k < 9; k++) w[k] = __ldg(wgt + ci * 9 + k);
        float s[3][6];
#pragma unroll
        for (int dy = 0; dy < 3; dy++)
#pragma unroll
            for (int dx = 0; dx < 6; dx++)
                s[dy][dx] = ys[ci * 1156 + (row + dy) * 34 + col0 + dx];
#pragma unroll
        for (int dy = 0; dy < 3; dy++) {
            float w0 = w[dy * 3], w1 = w[dy * 3 + 1], w2 = w[dy * 3 + 2];
            a0 += w0 * s[dy][0] + w1 * s[dy][1] + w2 * s[dy][2];
            a1 += w0 * s[dy][1] + w1 * s[dy][2] + w2 * s[dy][3];
            a2 += w0 * s[dy][2] + w1 * s[dy][3] + w2 * s[dy][4];
            a3 += w0 * s[dy][3] + w1 * s[dy][4] + w2 * s[dy][5];
        }
    }
    float* o = out + ((n * 128 + co) * 1024) + row * 32 + col0;
    o[0] = a0; o[1] = a1; o[2] = a2; o[3] = a3;
}

// ---------------- launcher (k_solve stays the 4th launch) -------------------
extern "C" void kernel_launch(void* const* d_in, const int* in_sizes, int n_in,
                              void* d_out, int out_size)
{
    const float* x    = (const float*)d_in[0];
    const float* a    = (const float*)d_in[1];
    const float* gw1  = (const float*)d_in[2];
    const float* gb1  = (const float*)d_in[3];
    const float* gw2  = (const float*)d_in[4];
    const float* gb2  = (const float*)d_in[5];
    const float* aw1  = (const float*)d_in[6];
    const float* ab1  = (const float*)d_in[7];
    const float* aw2  = (const float*)d_in[8];
    const float* ab2  = (const float*)d_in[9];
    const float* sw1  = (const float*)d_in[10];
    const float* sb1  = (const float*)d_in[11];
    const float* sw2  = (const float*)d_in[12];
    const float* sb2  = (const float*)d_in[13];
    const float* gn_g = (const float*)d_in[14];
    const float* gn_b = (const float*)d_in[15];
    const float* pw   = (const float*)d_in[16];
    const float* pb   = (const float*)d_in[17];
    float* out = (float*)d_out;

    k_conv1<<<128, 256>>>(x, gw1, gb1, aw1, ab1);
    k_conv2<<<96, 256>>>(gw2, gb2, aw2, ab2);
    k_build<<<32, 256>>>(a);
    k_solve<<<8, 544>>>();
    k_se<<<2, 256>>>(x, sw1, sb1, sw2, sb2);
    k_gn<<<2, 256>>>(gn_g, gn_b);
    k_convf<<<256, 256>>>(pw, pb, out);
}